// round 1
// baseline (speedup 1.0000x reference)
#include <cuda_runtime.h>
#include <cuda_bf16.h>

#define N_NODES 10000
#define N_EDGES 320000
#define DIM 256
#define HEADS 4
#define NEG_SLOPE 0.2f

// ------------------- static device scratch -------------------
__device__ float g_h[N_NODES * DIM];      // post-GEMM features of current layer
__device__ float g_feat[N_NODES * DIM];   // aggregated output -> next layer input
__device__ float g_es[N_NODES * HEADS];
__device__ float g_ed[N_NODES * HEADS];
__device__ int   g_deg[N_NODES];
__device__ int   g_rowptr[N_NODES + 1];
__device__ int   g_wp[N_NODES];
__device__ int   g_csrc[N_EDGES];

// ------------------- CSR construction -------------------
__global__ void zero_deg_kernel() {
    int i = blockIdx.x * blockDim.x + threadIdx.x;
    if (i < N_NODES) g_deg[i] = 0;
}

__global__ void hist_kernel(const int* __restrict__ dst) {
    int i = blockIdx.x * blockDim.x + threadIdx.x;
    if (i < N_EDGES) atomicAdd(&g_deg[dst[i]], 1);
}

__global__ void scan_kernel() {
    __shared__ int part[1024];
    int t = threadIdx.x;
    const int PER = (N_NODES + 1023) / 1024;  // 10
    int base = t * PER;
    int loc[PER];
    int sum = 0;
    #pragma unroll
    for (int i = 0; i < PER; i++) {
        int idx = base + i;
        int v = (idx < N_NODES) ? g_deg[idx] : 0;
        loc[i] = sum;
        sum += v;
    }
    part[t] = sum;
    __syncthreads();
    // Hillis-Steele inclusive scan
    for (int off = 1; off < 1024; off <<= 1) {
        int v = (t >= off) ? part[t - off] : 0;
        __syncthreads();
        part[t] += v;
        __syncthreads();
    }
    int pre = (t > 0) ? part[t - 1] : 0;
    #pragma unroll
    for (int i = 0; i < PER; i++) {
        int idx = base + i;
        if (idx < N_NODES) {
            int r = pre + loc[i];
            g_rowptr[idx] = r;
            g_wp[idx] = r;
        }
    }
    if (t == 1023) g_rowptr[N_NODES] = part[1023];
}

__global__ void scatter_kernel(const int* __restrict__ src, const int* __restrict__ dst) {
    int i = blockIdx.x * blockDim.x + threadIdx.x;
    if (i < N_EDGES) {
        int d = dst[i];
        int pos = atomicAdd(&g_wp[d], 1);
        g_csrc[pos] = src[i];
    }
}

// ------------------- GEMM: g_h = (in [+ x]) @ W -------------------
// A: [N_NODES, 256], W: [256, 256] row-major. first=1: A=x. first=0: A=g_feat+x.
#define BM 128
#define BN 64
#define BK 16

__global__ __launch_bounds__(256) void gemm_kernel(const float* __restrict__ X,
                                                   const float* __restrict__ W,
                                                   int first) {
    __shared__ float As[BK][BM];
    __shared__ float Bs[BK][BN];
    int tid = threadIdx.x;
    int bm = blockIdx.x;
    int bn = blockIdx.y;

    int tx = tid & 15;        // 0..15 col group
    int ty = tid >> 4;        // 0..15 row group
    int rowBase = ty * 8;     // TM=8
    int colBase = tx * 4;     // TN=4

    // A tile load indices: 128x16 elems, 2 float4 per thread
    int aRow = tid >> 2;            // 0..63
    int aK   = (tid & 3) * 4;       // 0,4,8,12
    // B tile load: 16x64 elems, 1 float4 per thread
    int bRow = tid >> 4;            // 0..15
    int bCol = (tid & 15) * 4;      // 0..60

    int gRow0 = bm * BM + aRow;
    int gRow1 = gRow0 + 64;

    float acc[8][4];
    #pragma unroll
    for (int i = 0; i < 8; i++)
        #pragma unroll
        for (int j = 0; j < 4; j++) acc[i][j] = 0.0f;

    for (int k0 = 0; k0 < DIM; k0 += BK) {
        float4 a0 = make_float4(0.f, 0.f, 0.f, 0.f);
        float4 a1 = make_float4(0.f, 0.f, 0.f, 0.f);
        if (gRow0 < N_NODES) {
            if (first) {
                a0 = *(const float4*)&X[gRow0 * DIM + k0 + aK];
            } else {
                float4 f = *(const float4*)&g_feat[gRow0 * DIM + k0 + aK];
                float4 xr = *(const float4*)&X[gRow0 * DIM + k0 + aK];
                a0 = make_float4(f.x + xr.x, f.y + xr.y, f.z + xr.z, f.w + xr.w);
            }
        }
        if (gRow1 < N_NODES) {
            if (first) {
                a1 = *(const float4*)&X[gRow1 * DIM + k0 + aK];
            } else {
                float4 f = *(const float4*)&g_feat[gRow1 * DIM + k0 + aK];
                float4 xr = *(const float4*)&X[gRow1 * DIM + k0 + aK];
                a1 = make_float4(f.x + xr.x, f.y + xr.y, f.z + xr.z, f.w + xr.w);
            }
        }
        As[aK + 0][aRow] = a0.x;
        As[aK + 1][aRow] = a0.y;
        As[aK + 2][aRow] = a0.z;
        As[aK + 3][aRow] = a0.w;
        As[aK + 0][aRow + 64] = a1.x;
        As[aK + 1][aRow + 64] = a1.y;
        As[aK + 2][aRow + 64] = a1.z;
        As[aK + 3][aRow + 64] = a1.w;

        float4 b = *(const float4*)&W[(k0 + bRow) * DIM + bn * BN + bCol];
        *(float4*)&Bs[bRow][bCol] = b;
        __syncthreads();

        #pragma unroll
        for (int k = 0; k < BK; k++) {
            float ra[8], rb[4];
            *(float4*)(&ra[0]) = *(const float4*)&As[k][rowBase];
            *(float4*)(&ra[4]) = *(const float4*)&As[k][rowBase + 4];
            *(float4*)(&rb[0]) = *(const float4*)&Bs[k][colBase];
            #pragma unroll
            for (int i = 0; i < 8; i++)
                #pragma unroll
                for (int j = 0; j < 4; j++)
                    acc[i][j] = fmaf(ra[i], rb[j], acc[i][j]);
        }
        __syncthreads();
    }

    int cRow = bm * BM + rowBase;
    int cCol = bn * BN + colBase;
    #pragma unroll
    for (int i = 0; i < 8; i++) {
        if (cRow + i < N_NODES) {
            float4 v = make_float4(acc[i][0], acc[i][1], acc[i][2], acc[i][3]);
            *(float4*)&g_h[(cRow + i) * DIM + cCol] = v;
        }
    }
}

// ------------------- attention scores -------------------
__global__ __launch_bounds__(256) void attn_kernel(const float* __restrict__ asrc,
                                                   const float* __restrict__ adst) {
    int n = blockIdx.x;
    int t = threadIdx.x;
    float h = g_h[n * DIM + t];
    float ps = h * asrc[t];
    float pd = h * adst[t];
    #pragma unroll
    for (int off = 16; off > 0; off >>= 1) {
        ps += __shfl_down_sync(0xFFFFFFFFu, ps, off);
        pd += __shfl_down_sync(0xFFFFFFFFu, pd, off);
    }
    __shared__ float ss[8], sd[8];
    if ((t & 31) == 0) {
        ss[t >> 5] = ps;
        sd[t >> 5] = pd;
    }
    __syncthreads();
    if (t < HEADS) {
        g_es[n * HEADS + t] = ss[2 * t] + ss[2 * t + 1];
        g_ed[n * HEADS + t] = sd[2 * t] + sd[2 * t + 1];
    }
}

// ------------------- segment softmax + aggregate -------------------
// mode 0: out = relu(agg + b) -> g_feat
// mode 1: out = relu(agg + b + x) -> dout
__global__ __launch_bounds__(128) void agg_kernel(const float* __restrict__ bias,
                                                  const float* __restrict__ x,
                                                  float* __restrict__ dout,
                                                  int mode) {
    int dst = blockIdx.x;
    int t = threadIdx.x;
    __shared__ float edd[HEADS], m_sh[HEADS], s_sh[HEADS];
    __shared__ float p_sh[32][HEADS];
    __shared__ int src_sh[32];
    __shared__ float red[128];

    int rs = g_rowptr[dst];
    int deg = g_rowptr[dst + 1] - rs;
    if (t < HEADS) edd[t] = g_ed[dst * HEADS + t];
    __syncthreads();

    int el = t >> 2;      // 0..31 edge lane
    int hd = t & 3;       // head for softmax work
    int head = t >> 5;    // head owning channels 2t,2t+1

    // pass 1: per-head max
    float mloc = -1e30f;
    for (int e = el; e < deg; e += 32) {
        int s = g_csrc[rs + e];
        float ev = g_es[s * HEADS + hd] + edd[hd];
        ev = (ev > 0.f) ? ev : NEG_SLOPE * ev;
        mloc = fmaxf(mloc, ev);
    }
    red[t] = mloc;
    __syncthreads();
    if (t < HEADS) {
        float mm = -1e30f;
        #pragma unroll
        for (int i = 0; i < 32; i++) mm = fmaxf(mm, red[i * 4 + t]);
        m_sh[t] = mm;
    }
    __syncthreads();

    // pass 2: exp + weighted aggregate in chunks of 32 edges
    float2 acc = make_float2(0.f, 0.f);
    float sloc = 0.f;
    for (int e0 = 0; e0 < deg; e0 += 32) {
        int nE = min(32, deg - e0);
        if (el < nE) {
            int s = g_csrc[rs + e0 + el];
            if (hd == 0) src_sh[el] = s;
            float ev = g_es[s * HEADS + hd] + edd[hd];
            ev = (ev > 0.f) ? ev : NEG_SLOPE * ev;
            float p = __expf(ev - m_sh[hd]);
            p_sh[el][hd] = p;
            sloc += p;
        }
        __syncthreads();
        for (int e = 0; e < nE; e++) {
            float2 hv = *(const float2*)&g_h[src_sh[e] * DIM + 2 * t];
            float a = p_sh[e][head];
            acc.x = fmaf(a, hv.x, acc.x);
            acc.y = fmaf(a, hv.y, acc.y);
        }
        __syncthreads();
    }

    red[t] = sloc;
    __syncthreads();
    if (t < HEADS) {
        float ssum = 0.f;
        #pragma unroll
        for (int i = 0; i < 32; i++) ssum += red[i * 4 + t];
        s_sh[t] = ssum;
    }
    __syncthreads();

    float inv = 1.0f / (s_sh[head] + 1e-16f);
    int c = 2 * t;
    float o0 = acc.x * inv + bias[c];
    float o1 = acc.y * inv + bias[c + 1];
    if (mode == 1) {
        o0 += x[dst * DIM + c];
        o1 += x[dst * DIM + c + 1];
        o0 = fmaxf(o0, 0.f);
        o1 = fmaxf(o1, 0.f);
        dout[dst * DIM + c] = o0;
        dout[dst * DIM + c + 1] = o1;
    } else {
        o0 = fmaxf(o0, 0.f);
        o1 = fmaxf(o1, 0.f);
        g_feat[dst * DIM + c] = o0;
        g_feat[dst * DIM + c + 1] = o1;
    }
}

// ------------------- launch -------------------
extern "C" void kernel_launch(void* const* d_in, const int* in_sizes, int n_in,
                              void* d_out, int out_size) {
    const float* x  = (const float*)d_in[0];
    const int*   ei = (const int*)d_in[1];
    const float* W1 = (const float*)d_in[2];
    const float* as1 = (const float*)d_in[3];
    const float* ad1 = (const float*)d_in[4];
    const float* b1 = (const float*)d_in[5];
    const float* W2 = (const float*)d_in[6];
    const float* as2 = (const float*)d_in[7];
    const float* ad2 = (const float*)d_in[8];
    const float* b2 = (const float*)d_in[9];
    const float* W3 = (const float*)d_in[10];
    const float* as3 = (const float*)d_in[11];
    const float* ad3 = (const float*)d_in[12];
    const float* b3 = (const float*)d_in[13];
    const float* WN = (const float*)d_in[14];
    const float* asN = (const float*)d_in[15];
    const float* adN = (const float*)d_in[16];
    const float* bN = (const float*)d_in[17];

    const int* src = ei;
    const int* dst = ei + N_EDGES;
    float* out = (float*)d_out;

    // CSR build (same every replay — deterministic inputs)
    zero_deg_kernel<<<(N_NODES + 255) / 256, 256>>>();
    hist_kernel<<<(N_EDGES + 255) / 256, 256>>>(dst);
    scan_kernel<<<1, 1024>>>();
    scatter_kernel<<<(N_EDGES + 255) / 256, 256>>>(src, dst);

    dim3 gemmGrid((N_NODES + BM - 1) / BM, DIM / BN);

    // Layer 1
    gemm_kernel<<<gemmGrid, 256>>>(x, W1, 1);
    attn_kernel<<<N_NODES, 256>>>(as1, ad1);
    agg_kernel<<<N_NODES, 128>>>(b1, x, out, 0);
    // Layer 2
    gemm_kernel<<<gemmGrid, 256>>>(x, W2, 0);
    attn_kernel<<<N_NODES, 256>>>(as2, ad2);
    agg_kernel<<<N_NODES, 128>>>(b2, x, out, 0);
    // Layer 3
    gemm_kernel<<<gemmGrid, 256>>>(x, W3, 0);
    attn_kernel<<<N_NODES, 256>>>(as3, ad3);
    agg_kernel<<<N_NODES, 128>>>(b3, x, out, 0);
    // Layer 4 (final: residual + relu into d_out)
    gemm_kernel<<<gemmGrid, 256>>>(x, WN, 0);
    attn_kernel<<<N_NODES, 256>>>(asN, adN);
    agg_kernel<<<N_NODES, 128>>>(bN, x, out, 1);
}